// round 15
// baseline (speedup 1.0000x reference)
#include <cuda_runtime.h>
#include <cuda_bf16.h>
#include <math.h>
#include <stdint.h>

// ---------------- problem constants ----------------
constexpr int Bn   = 32;
constexpr int Hh   = 56;
constexpr int Wd   = 56;
constexpr int Cc   = 384;
constexpr int NHd  = 12;
constexpr int WS   = 7;
constexpr int SS   = 3;
constexpr int Ntok = WS * WS;            // 49
constexpr int NWim = (Hh/WS) * (Wd/WS);  // 64
constexpr int HD   = Cc / NHd;           // 32
constexpr int MLPH = 4 * Cc;             // 1536
constexpr int Mrows = Bn * Hh * Wd;      // 100352
constexpr int ThreeC = 3 * Cc;           // 1152

// ---------------- scratch (device globals) ----------------
__device__ __nv_bfloat16 g_xw  [(size_t)Mrows * Cc];
__device__ __nv_bfloat16 g_qkv [(size_t)Mrows * ThreeC];
__device__ __nv_bfloat16 g_attb[(size_t)Mrows * Cc];
__device__ float         g_x2w [(size_t)Mrows * Cc];
__device__ __nv_bfloat16 g_h   [(size_t)Mrows * Cc];
__device__ __nv_bfloat16 g_f1  [(size_t)Mrows * MLPH];
constexpr size_t WT_QKV  = 0;
constexpr size_t WT_PROJ = WT_QKV  + (size_t)Cc * ThreeC;
constexpr size_t WT_FC1  = WT_PROJ + (size_t)Cc * Cc;
constexpr size_t WT_FC2  = WT_FC1  + (size_t)Cc * MLPH;
__device__ __nv_bfloat16 g_wt[WT_FC2 + (size_t)MLPH * Cc];

// ---------------- helpers ----------------
__device__ __forceinline__ uint32_t smem_u32(const void* p) {
    uint32_t a;
    asm("{ .reg .u64 t; cvta.to.shared.u64 t, %1; cvt.u32.u64 %0, t; }" : "=r"(a) : "l"(p));
    return a;
}
#define CP16(dst, src) asm volatile("cp.async.cg.shared.global [%0], [%1], 16;\n" :: "r"(dst), "l"(src))
#define CP_COMMIT()    asm volatile("cp.async.commit_group;\n" ::: "memory")
#define CP_WAIT2()     asm volatile("cp.async.wait_group 2;\n" ::: "memory")

__device__ __forceinline__ uint32_t swz64(uint32_t off) {
    return off ^ ((off >> 3) & 0x30);
}
__device__ __forceinline__ uint32_t swz128(uint32_t off) {
    return off ^ ((off >> 3) & 0x70);
}
__device__ __forceinline__ void ldsm_x4(uint32_t* r, uint32_t addr) {
    asm volatile("ldmatrix.sync.aligned.m8n8.x4.shared.b16 {%0,%1,%2,%3}, [%4];"
        : "=r"(r[0]), "=r"(r[1]), "=r"(r[2]), "=r"(r[3]) : "r"(addr));
}
__device__ __forceinline__ void ldsm_x4_t(uint32_t* r, uint32_t addr) {
    asm volatile("ldmatrix.sync.aligned.m8n8.x4.trans.shared.b16 {%0,%1,%2,%3}, [%4];"
        : "=r"(r[0]), "=r"(r[1]), "=r"(r[2]), "=r"(r[3]) : "r"(addr));
}
__device__ __forceinline__ void mma_bf16(float* d, const uint32_t* a,
                                         uint32_t b0, uint32_t b1) {
    asm volatile(
        "mma.sync.aligned.m16n8k16.row.col.f32.bf16.bf16.f32 "
        "{%0,%1,%2,%3}, {%4,%5,%6,%7}, {%8,%9}, {%0,%1,%2,%3};\n"
        : "+f"(d[0]), "+f"(d[1]), "+f"(d[2]), "+f"(d[3])
        : "r"(a[0]), "r"(a[1]), "r"(a[2]), "r"(a[3]), "r"(b0), "r"(b1));
}
__device__ __forceinline__ __nv_bfloat162 pack_bf2(float a, float b) {
    return __floats2bfloat162_rn(a, b);
}
// window-order token -> image-order token
__device__ __forceinline__ int w2i(int t) {
    int widx = t / Ntok, n = t - widx * Ntok;
    int b = widx >> 6, wi = widx & 63;
    int r = (wi >> 3) * WS + n / WS;
    int c = (wi & 7) * WS + n % WS;
    int sh = r + SS; if (sh >= Hh) sh -= Hh;
    int sw = c + SS; if (sw >= Wd) sw -= Wd;
    return b * (Hh * Wd) + sh * Wd + sw;
}

// ---------------- single-launch weight transpose + bf16 ----------------
__global__ void k_transpose_all(const float* __restrict__ qkv_w, const float* __restrict__ proj_w,
                                const float* __restrict__ fc1_w, const float* __restrict__ fc2_w,
                                __nv_bfloat16* __restrict__ wt) {
    int t = blockIdx.x;
    const float* W; __nv_bfloat16* Wt; int K, N, tile, ntx;
    if (t < 432)       { W = qkv_w;  Wt = wt + WT_QKV;  K = Cc;   N = ThreeC; tile = t;        ntx = 36; }
    else if (t < 576)  { W = proj_w; Wt = wt + WT_PROJ; K = Cc;   N = Cc;     tile = t - 432;  ntx = 12; }
    else if (t < 1152) { W = fc1_w;  Wt = wt + WT_FC1;  K = Cc;   N = MLPH;   tile = t - 576;  ntx = 48; }
    else               { W = fc2_w;  Wt = wt + WT_FC2;  K = MLPH; N = Cc;     tile = t - 1152; ntx = 12; }
    int n0 = (tile % ntx) * 32, k0 = (tile / ntx) * 32;

    __shared__ float sm[32][33];
    int tx = threadIdx.x, ty = threadIdx.y;
    #pragma unroll
    for (int i = 0; i < 32; i += 8)
        sm[ty + i][tx] = W[(size_t)(k0 + ty + i) * N + n0 + tx];
    __syncthreads();
    #pragma unroll
    for (int i = 0; i < 32; i += 8)
        Wt[(size_t)(n0 + ty + i) * K + k0 + tx] = __float2bfloat16_rn(sm[tx][ty + i]);
}

// ---------------- bf16 mma.sync GEMM, 128x128 tile, 256 thr, 2 CTAs/SM ----------
// 4-stage cp.async (64KB), 8 warps (4M x 2N), warp tile 32x64, BK=32.
constexpr int GBM = 128, GBN = 128;
constexpr int ASTB = GBM * 64;            // 8192
constexpr int BSTB = GBN * 64;            // 8192
constexpr int STB  = ASTB + BSTB;         // 16384
constexpr int SMEM_GEMM = 4 * STB;        // 65536

template <int OT, typename OutT>
__global__ __launch_bounds__(256, 2)
void k_gemm_bf(const __nv_bfloat16* __restrict__ A, const __nv_bfloat16* __restrict__ Wt,
               const float* __restrict__ bias, const float* __restrict__ res,
               OutT* __restrict__ Cm, int M, int N, int K) {
    extern __shared__ char smem[];
    uint32_t sbase = smem_u32(smem);

    const int tid  = threadIdx.x;
    const int lane = tid & 31, warp = tid >> 5;
    const int wm = warp >> 1, wn = warp & 1;
    const int g = lane >> 2, q = lane & 3;
    const int row0 = blockIdx.y * GBM, col0 = blockIdx.x * GBN;
    const int KT = K / 32;

    const __nv_bfloat16* Ab = A  + (size_t)row0 * K;
    const __nv_bfloat16* Bb = Wt + (size_t)col0 * K;

    uint32_t a_off[2], b_off[4];
    {
        int rowa = wm * 32 + (lane & 15);
        int sega = lane >> 4;
        #pragma unroll
        for (int mi = 0; mi < 2; mi++)
            a_off[mi] = swz64((uint32_t)(rowa + mi * 16) * 64 + sega * 16);
        int rowb = wn * 64 + (lane & 7) + ((lane >> 4) << 3);
        int segb = (lane >> 3) & 1;
        #pragma unroll
        for (int p = 0; p < 4; p++)
            b_off[p] = ASTB + swz64((uint32_t)(rowb + p * 16) * 64 + segb * 16);
    }

    float acc[2][8][4];
    #pragma unroll
    for (int i = 0; i < 2; i++)
        #pragma unroll
        for (int j = 0; j < 8; j++)
            #pragma unroll
            for (int r = 0; r < 4; r++) acc[i][j][r] = 0.f;

    auto load_stage = [&](int kt, int s) {
        uint32_t sA = sbase + (uint32_t)s * STB;
        uint32_t sB = sA + ASTB;
        const __nv_bfloat16* Ap = Ab + kt * 32;
        const __nv_bfloat16* Bp = Bb + kt * 32;
        #pragma unroll
        for (int i = 0; i < 2; i++) {
            int c = tid + i * 256, r = c >> 2, cc = c & 3;
            CP16(sA + swz64((uint32_t)(r * 64 + cc * 16)), Ap + (size_t)r * K + cc * 8);
        }
        #pragma unroll
        for (int i = 0; i < 2; i++) {
            int c = tid + i * 256, r = c >> 2, cc = c & 3;
            CP16(sB + swz64((uint32_t)(r * 64 + cc * 16)), Bp + (size_t)r * K + cc * 8);
        }
    };

    load_stage(0, 0); CP_COMMIT();
    load_stage(1, 1); CP_COMMIT();
    load_stage(2, 2); CP_COMMIT();

    for (int kt = 0; kt < KT; kt++) {
        CP_WAIT2();
        __syncthreads();
        uint32_t st = sbase + (uint32_t)(kt & 3) * STB;
        #pragma unroll
        for (int ks = 0; ks < 2; ks++) {
            const uint32_t kx = (uint32_t)ks * 0x20;
            uint32_t a[2][4], b[4][4];
            #pragma unroll
            for (int mi = 0; mi < 2; mi++) ldsm_x4(a[mi], st + (a_off[mi] ^ kx));
            #pragma unroll
            for (int p = 0; p < 4; p++)    ldsm_x4(b[p],  st + (b_off[p]  ^ kx));
            #pragma unroll
            for (int mi = 0; mi < 2; mi++)
                #pragma unroll
                for (int p = 0; p < 4; p++) {
                    mma_bf16(acc[mi][2 * p],     a[mi], b[p][0], b[p][1]);
                    mma_bf16(acc[mi][2 * p + 1], a[mi], b[p][2], b[p][3]);
                }
        }
        if (kt + 3 < KT) load_stage(kt + 3, (kt + 3) & 3);
        CP_COMMIT();
    }

    // ---- epilogue ----
    #pragma unroll
    for (int mi = 0; mi < 2; mi++) {
        int rA = row0 + wm * 32 + mi * 16 + g;
        int rB = rA + 8;
        const float* resA = nullptr; const float* resB = nullptr;
        OutT* outA; OutT* outB;
        if (OT == 4) {
            resA = res + (size_t)w2i(rA) * N;
            resB = res + (size_t)w2i(rB) * N;
            outA = Cm + (size_t)rA * N; outB = Cm + (size_t)rB * N;
        } else if (OT == 5) {
            resA = res + (size_t)rA * N;
            resB = res + (size_t)rB * N;
            outA = Cm + (size_t)w2i(rA) * N; outB = Cm + (size_t)w2i(rB) * N;
        } else {
            outA = Cm + (size_t)rA * N; outB = Cm + (size_t)rB * N;
        }
        #pragma unroll
        for (int ni = 0; ni < 8; ni++) {
            int c = col0 + wn * 64 + ni * 8 + q * 2;
            float b0 = bias[c], b1 = bias[c + 1];
            float v0 = acc[mi][ni][0] + b0;
            float v1 = acc[mi][ni][1] + b1;
            float v2 = acc[mi][ni][2] + b0;
            float v3 = acc[mi][ni][3] + b1;
            if (OT == 1) {
                v0 = 0.5f * v0 * (1.f + erff(v0 * 0.70710678118654752f));
                v1 = 0.5f * v1 * (1.f + erff(v1 * 0.70710678118654752f));
                v2 = 0.5f * v2 * (1.f + erff(v2 * 0.70710678118654752f));
                v3 = 0.5f * v3 * (1.f + erff(v3 * 0.70710678118654752f));
            }
            if (OT >= 4) {
                float2 ra = *(const float2*)&resA[c];
                float2 rb = *(const float2*)&resB[c];
                v0 += ra.x; v1 += ra.y; v2 += rb.x; v3 += rb.y;
            }
            if (OT <= 1) {
                *(__nv_bfloat162*)&((__nv_bfloat16*)outA)[c] = pack_bf2(v0, v1);
                *(__nv_bfloat162*)&((__nv_bfloat16*)outB)[c] = pack_bf2(v2, v3);
            } else {
                *(float2*)&((float*)outA)[c] = make_float2(v0, v1);
                *(float2*)&((float*)outB)[c] = make_float2(v2, v3);
            }
        }
    }
}

// ---------------- LN, warp-per-row (8 rows / 256-thr block) ----------------
// GATHER: ln1 reads x at image-order via w2i; ln2 reads linear.
template <bool GATHER>
__global__ __launch_bounds__(256)
void k_ln(const float* __restrict__ x, const float* __restrict__ w,
          const float* __restrict__ bi, __nv_bfloat16* __restrict__ out) {
    int warp = threadIdx.x >> 5, lane = threadIdx.x & 31;
    int t = blockIdx.x * 8 + warp;
    const float* src = x + (size_t)(GATHER ? w2i(t) : t) * Cc;

    float2 v[6]; float s = 0.f, s2 = 0.f;
    #pragma unroll
    for (int i = 0; i < 6; i++) {
        v[i] = *(const float2*)&src[(lane + i * 32) * 2];
        s  += v[i].x + v[i].y;
        s2 += v[i].x * v[i].x + v[i].y * v[i].y;
    }
    #pragma unroll
    for (int o = 16; o > 0; o >>= 1) {
        s  += __shfl_xor_sync(0xFFFFFFFFu, s,  o);
        s2 += __shfl_xor_sync(0xFFFFFFFFu, s2, o);
    }
    float mean = s * (1.f / Cc);
    float var  = s2 * (1.f / Cc) - mean * mean;
    float inv  = rsqrtf(var + 1e-5f);
    __nv_bfloat162* dst = (__nv_bfloat162*)(out + (size_t)t * Cc);
    #pragma unroll
    for (int i = 0; i < 6; i++) {
        int c = (lane + i * 32) * 2;
        float2 wv = *(const float2*)&w[c];
        float2 bv = *(const float2*)&bi[c];
        float a = (v[i].x - mean) * inv * wv.x + bv.x;
        float b = (v[i].y - mean) * inv * wv.y + bv.y;
        dst[lane + i * 32] = pack_bf2(a, b);
    }
}

// ---------------- tensor-core attention with bias+mask lookup table -------
// smem: Q 0 | K 4096 | V 8192 | table/P 12288 (8KB: table bf16[64][64] then P)
//       | sbias 20480 | sreg 21160
__global__ __launch_bounds__(128)
void k_attn(const __nv_bfloat16* __restrict__ qkv, const float* __restrict__ rpb,
            __nv_bfloat16* __restrict__ out) {
    __shared__ __align__(1024) char smem[21504];
    uint32_t sb = smem_u32(smem);
    float* sbias = (float*)(smem + 20480);
    int*   sreg  = (int*)(smem + 21160);

    int blk = blockIdx.x;
    int widx = blk / NHd, hh = blk % NHd;
    int wi = widx % NWim;
    int wh = wi / 8, ww = wi % 8;
    int tid = threadIdx.x, lane = tid & 31, warp = tid >> 5;
    int g = lane >> 2, q = lane & 3;

    // ---- load Q,K,V (rows 0-48) + zero pad rows 49-63 ----
    const __nv_bfloat16* base0 = qkv + (size_t)(widx * Ntok) * ThreeC + hh * HD;
    for (int idx = tid; idx < 196; idx += 128) {
        int row = idx >> 2, seg = idx & 3;
        const __nv_bfloat16* p = base0 + (size_t)row * ThreeC + seg * 8;
        uint32_t d = swz64((uint32_t)(row * 64 + seg * 16));
        *(uint4*)(smem + d)        = *(const uint4*)(p);
        *(uint4*)(smem + 4096 + d) = *(const uint4*)(p + Cc);
        *(uint4*)(smem + 8192 + d) = *(const uint4*)(p + 2 * Cc);
    }
    for (int idx = 196 + tid; idx < 256; idx += 128) {
        int row = idx >> 2, seg = idx & 3;
        uint32_t d = swz64((uint32_t)(row * 64 + seg * 16));
        uint4 z = make_uint4(0, 0, 0, 0);
        *(uint4*)(smem + d)        = z;
        *(uint4*)(smem + 4096 + d) = z;
        *(uint4*)(smem + 8192 + d) = z;
    }
    if (tid < Ntok) {
        int r = wh * WS + tid / WS, c = ww * WS + tid % WS;
        int hr = (r < Hh - WS) ? 0 : ((r < Hh - SS) ? 1 : 2);
        int wr = (c < Wd - WS) ? 0 : ((c < Wd - SS) ? 1 : 2);
        sreg[tid] = hr * 3 + wr;
    }
    for (int idx = tid; idx < 169; idx += 128)
        sbias[idx] = rpb[idx * NHd + hh];
    __syncthreads();

    // ---- build bias+mask table bf16[64][64] in P region ----
    for (int idx = tid; idx < 4096; idx += 128) {
        int i = idx >> 6, j = idx & 63;
        float v = -1e4f;
        if (i < Ntok && j < Ntok) {
            int id = i / 7, im = i - id * 7;
            int jd = j / 7, jm = j - jd * 7;
            v = sbias[(id - jd + 6) * 13 + (im - jm + 6)];
            if (sreg[i] != sreg[j]) v -= 100.f;
        }
        *(__nv_bfloat16*)(smem + 12288 + idx * 2) = __float2bfloat16_rn(v);
    }

    // ---- S = Q K^T (64x64, K=32) ----
    float acc[8][4];
    #pragma unroll
    for (int i = 0; i < 8; i++)
        #pragma unroll
        for (int r = 0; r < 4; r++) acc[i][r] = 0.f;
    {
        uint32_t aoff = swz64((uint32_t)(warp * 16 + (lane & 15)) * 64 + (lane >> 4) * 16);
        int rowb = (lane & 7) + ((lane >> 4) << 3);
        uint32_t segb = ((lane >> 3) & 1) * 16;
        uint32_t boff[4];
        #pragma unroll
        for (int p = 0; p < 4; p++)
            boff[p] = 4096u + swz64((uint32_t)(rowb + p * 16) * 64 + segb);
        #pragma unroll
        for (int kk = 0; kk < 2; kk++) {
            uint32_t kx = (uint32_t)kk * 32;
            uint32_t a[4];
            ldsm_x4(a, sb + (aoff ^ kx));
            #pragma unroll
            for (int p = 0; p < 4; p++) {
                uint32_t b[4];
                ldsm_x4(b, sb + (boff[p] ^ kx));
                mma_bf16(acc[2 * p],     a, b[0], b[1]);
                mma_bf16(acc[2 * p + 1], a, b[2], b[3]);
            }
        }
    }
    __syncthreads();   // table complete + mma done before softmax reads table

    // ---- softmax via table lookups ----
    const float scl = 0.17677669529663687f;
    int i1 = warp * 16 + g, i2 = i1 + 8;
    bool v1 = i1 < Ntok, v2 = i2 < Ntok;
    const __nv_bfloat162* st1 = (const __nv_bfloat162*)(smem + 12288 + i1 * 128);
    const __nv_bfloat162* st2 = (const __nv_bfloat162*)(smem + 12288 + i2 * 128);
    float mx1 = -1e30f, mx2 = -1e30f;
    #pragma unroll
    for (int ni = 0; ni < 8; ni++) {
        int jp = ni * 4 + q;
        float2 b1 = __bfloat1622float2(st1[jp]);
        float2 b2 = __bfloat1622float2(st2[jp]);
        float t;
        t = fmaf(acc[ni][0], scl, b1.x); acc[ni][0] = t; mx1 = fmaxf(mx1, t);
        t = fmaf(acc[ni][1], scl, b1.y); acc[ni][1] = t; mx1 = fmaxf(mx1, t);
        t = fmaf(acc[ni][2], scl, b2.x); acc[ni][2] = t; mx2 = fmaxf(mx2, t);
        t = fmaf(acc[ni][3], scl, b2.y); acc[ni][3] = t; mx2 = fmaxf(mx2, t);
    }
    mx1 = fmaxf(mx1, __shfl_xor_sync(0xFFFFFFFFu, mx1, 1));
    mx1 = fmaxf(mx1, __shfl_xor_sync(0xFFFFFFFFu, mx1, 2));
    mx2 = fmaxf(mx2, __shfl_xor_sync(0xFFFFFFFFu, mx2, 1));
    mx2 = fmaxf(mx2, __shfl_xor_sync(0xFFFFFFFFu, mx2, 2));
    float s1 = 0.f, s2 = 0.f;
    #pragma unroll
    for (int ni = 0; ni < 8; ni++) {
        float e0 = __expf(acc[ni][0] - mx1); acc[ni][0] = e0;
        float e1 = __expf(acc[ni][1] - mx1); acc[ni][1] = e1; s1 += e0 + e1;
        float e2 = __expf(acc[ni][2] - mx2); acc[ni][2] = e2;
        float e3 = __expf(acc[ni][3] - mx2); acc[ni][3] = e3; s2 += e2 + e3;
    }
    s1 += __shfl_xor_sync(0xFFFFFFFFu, s1, 1);
    s1 += __shfl_xor_sync(0xFFFFFFFFu, s1, 2);
    s2 += __shfl_xor_sync(0xFFFFFFFFu, s2, 1);
    s2 += __shfl_xor_sync(0xFFFFFFFFu, s2, 2);
    float n1 = v1 ? (1.f / s1) : 0.f;
    float n2 = v2 ? (1.f / s2) : 0.f;
    __syncwarp();   // all table reads for this warp's rows done before P overwrite

    // ---- store P (bf16) into swizzled 128B-row buffer (warp-private rows) ----
    #pragma unroll
    for (int ni = 0; ni < 8; ni++) {
        uint32_t cb = (uint32_t)(ni * 8 + q * 2) * 2;
        uint32_t o1 = 12288u + swz128((uint32_t)i1 * 128 + cb);
        uint32_t o2 = 12288u + swz128((uint32_t)i2 * 128 + cb);
        *(__nv_bfloat162*)(smem + o1) = pack_bf2(acc[ni][0] * n1, acc[ni][1] * n1);
        *(__nv_bfloat162*)(smem + o2) = pack_bf2(acc[ni][2] * n2, acc[ni][3] * n2);
    }
    __syncwarp();

    // ---- O = P V  (64x32, K=64) ----
    float acc2[4][4];
    #pragma unroll
    for (int i = 0; i < 4; i++)
        #pragma unroll
        for (int r = 0; r < 4; r++) acc2[i][r] = 0.f;
    {
        uint32_t a2off = 12288u + swz128((uint32_t)(warp * 16 + (lane & 15)) * 128 + (lane >> 4) * 16);
        int rv = (lane & 7) + ((lane >> 3) & 1) * 8;
        uint32_t dv8 = (uint32_t)((lane >> 4) << 3);
        uint32_t voff0 = 8192u + swz64((uint32_t)rv * 64 + dv8 * 2);
        uint32_t voff1 = 8192u + swz64((uint32_t)rv * 64 + (16 + dv8) * 2);
        #pragma unroll
        for (int ks = 0; ks < 4; ks++) {
            uint32_t a2[4], b0[4], b1[4];
            ldsm_x4(a2, sb + (a2off ^ ((uint32_t)ks * 32)));
            ldsm_x4_t(b0, sb + voff0 + (uint32_t)ks * 1024);
            ldsm_x4_t(b1, sb + voff1 + (uint32_t)ks * 1024);
            mma_bf16(acc2[0], a2, b0[0], b0[1]);
            mma_bf16(acc2[1], a2, b0[2], b0[3]);
            mma_bf16(acc2[2], a2, b1[0], b1[1]);
            mma_bf16(acc2[3], a2, b1[2], b1[3]);
        }
    }

    if (v1) {
        __nv_bfloat16* d = out + (size_t)(widx * Ntok + i1) * Cc + hh * HD + q * 2;
        #pragma unroll
        for (int dt = 0; dt < 4; dt++)
            *(__nv_bfloat162*)(d + dt * 8) = pack_bf2(acc2[dt][0], acc2[dt][1]);
    }
    if (v2) {
        __nv_bfloat16* d = out + (size_t)(widx * Ntok + i2) * Cc + hh * HD + q * 2;
        #pragma unroll
        for (int dt = 0; dt < 4; dt++)
            *(__nv_bfloat162*)(d + dt * 8) = pack_bf2(acc2[dt][2], acc2[dt][3]);
    }
}

// ---------------- host launch ----------------
extern "C" void kernel_launch(void* const* d_in, const int* in_sizes, int n_in,
                              void* d_out, int out_size) {
    const float* x      = (const float*)d_in[0];
    const float* n1w    = (const float*)d_in[1];
    const float* n1b    = (const float*)d_in[2];
    const float* qkv_w  = (const float*)d_in[3];
    const float* qkv_b  = (const float*)d_in[4];
    const float* rpb    = (const float*)d_in[5];
    const float* proj_w = (const float*)d_in[6];
    const float* proj_b = (const float*)d_in[7];
    const float* n2w    = (const float*)d_in[8];
    const float* n2b    = (const float*)d_in[9];
    const float* fc1_w  = (const float*)d_in[10];
    const float* fc1_b  = (const float*)d_in[11];
    const float* fc2_w  = (const float*)d_in[12];
    const float* fc2_b  = (const float*)d_in[13];
    float* out = (float*)d_out;

    __nv_bfloat16 *p_xw, *p_qkv, *p_attb, *p_h, *p_f1, *p_wt;
    float *p_x2w;
    cudaGetSymbolAddress((void**)&p_xw,   g_xw);
    cudaGetSymbolAddress((void**)&p_qkv,  g_qkv);
    cudaGetSymbolAddress((void**)&p_attb, g_attb);
    cudaGetSymbolAddress((void**)&p_x2w,  g_x2w);
    cudaGetSymbolAddress((void**)&p_h,    g_h);
    cudaGetSymbolAddress((void**)&p_f1,   g_f1);
    cudaGetSymbolAddress((void**)&p_wt,   g_wt);

    cudaFuncSetAttribute(k_gemm_bf<0, __nv_bfloat16>, cudaFuncAttributeMaxDynamicSharedMemorySize, SMEM_GEMM);
    cudaFuncSetAttribute(k_gemm_bf<1, __nv_bfloat16>, cudaFuncAttributeMaxDynamicSharedMemorySize, SMEM_GEMM);
    cudaFuncSetAttribute(k_gemm_bf<4, float>,         cudaFuncAttributeMaxDynamicSharedMemorySize, SMEM_GEMM);
    cudaFuncSetAttribute(k_gemm_bf<5, float>,         cudaFuncAttributeMaxDynamicSharedMemorySize, SMEM_GEMM);

    // 0. transpose + bf16 weights
    k_transpose_all<<<1728, dim3(32, 8)>>>(qkv_w, proj_w, fc1_w, fc2_w, p_wt);

    // 1. LN1 + shift + window partition (gather)
    k_ln<true><<<Mrows / 8, 256>>>(x, n1w, n1b, p_xw);

    // 2. QKV GEMM -> bf16
    k_gemm_bf<0, __nv_bfloat16><<<dim3(ThreeC/GBN, Mrows/GBM), 256, SMEM_GEMM>>>(
        p_xw, p_wt + WT_QKV, qkv_b, nullptr, p_qkv, Mrows, ThreeC, Cc);

    // 3. tensor-core windowed attention -> bf16
    k_attn<<<(Bn * NWim) * NHd, 128>>>(p_qkv, rpb, p_attb);

    // 4. proj GEMM + gathered residual -> x2w (f32, window order)
    k_gemm_bf<4, float><<<dim3(Cc/GBN, Mrows/GBM), 256, SMEM_GEMM>>>(
        p_attb, p_wt + WT_PROJ, proj_b, x, p_x2w, Mrows, Cc, Cc);

    // 5. LN2 (window order)
    k_ln<false><<<Mrows / 8, 256>>>(p_x2w, n2w, n2b, p_h);

    // 6. fc1 GEMM + GELU -> bf16
    k_gemm_bf<1, __nv_bfloat16><<<dim3(MLPH/GBN, Mrows/GBM), 256, SMEM_GEMM>>>(
        p_h, p_wt + WT_FC1, fc1_b, nullptr, p_f1, Mrows, MLPH, Cc);

    // 7. fc2 GEMM + bias + residual, scattered to image order -> d_out
    k_gemm_bf<5, float><<<dim3(Cc/GBN, Mrows/GBM), 256, SMEM_GEMM>>>(
        p_f1, p_wt + WT_FC2, fc2_b, p_x2w, out, Mrows, Cc, MLPH);
}

// round 16
// speedup vs baseline: 1.0665x; 1.0665x over previous
#include <cuda_runtime.h>
#include <cuda_bf16.h>
#include <math.h>
#include <stdint.h>

// ---------------- problem constants ----------------
constexpr int Bn   = 32;
constexpr int Hh   = 56;
constexpr int Wd   = 56;
constexpr int Cc   = 384;
constexpr int NHd  = 12;
constexpr int WS   = 7;
constexpr int SS   = 3;
constexpr int Ntok = WS * WS;            // 49
constexpr int NWim = (Hh/WS) * (Wd/WS);  // 64
constexpr int HD   = Cc / NHd;           // 32
constexpr int MLPH = 4 * Cc;             // 1536
constexpr int Mrows = Bn * Hh * Wd;      // 100352
constexpr int ThreeC = 3 * Cc;           // 1152

// ---------------- scratch (device globals) ----------------
__device__ __nv_bfloat16 g_xw  [(size_t)Mrows * Cc];
__device__ __nv_bfloat16 g_qkv [(size_t)Mrows * ThreeC];
__device__ __nv_bfloat16 g_attb[(size_t)Mrows * Cc];
__device__ float         g_x2w [(size_t)Mrows * Cc];
__device__ __nv_bfloat16 g_h   [(size_t)Mrows * Cc];
__device__ __nv_bfloat16 g_f1  [(size_t)Mrows * MLPH];
__device__ __nv_bfloat16 g_tbl [4 * NHd * 64 * 64];       // bias+mask logit tables
constexpr size_t WT_QKV  = 0;
constexpr size_t WT_PROJ = WT_QKV  + (size_t)Cc * ThreeC;
constexpr size_t WT_FC1  = WT_PROJ + (size_t)Cc * Cc;
constexpr size_t WT_FC2  = WT_FC1  + (size_t)Cc * MLPH;
__device__ __nv_bfloat16 g_wt[WT_FC2 + (size_t)MLPH * Cc];

// ---------------- helpers ----------------
__device__ __forceinline__ uint32_t smem_u32(const void* p) {
    uint32_t a;
    asm("{ .reg .u64 t; cvta.to.shared.u64 t, %1; cvt.u32.u64 %0, t; }" : "=r"(a) : "l"(p));
    return a;
}
#define CP16(dst, src) asm volatile("cp.async.cg.shared.global [%0], [%1], 16;\n" :: "r"(dst), "l"(src))
#define CP_COMMIT()    asm volatile("cp.async.commit_group;\n" ::: "memory")
#define CP_WAIT2()     asm volatile("cp.async.wait_group 2;\n" ::: "memory")

__device__ __forceinline__ uint32_t swz64(uint32_t off) {
    return off ^ ((off >> 3) & 0x30);
}
__device__ __forceinline__ uint32_t swz128(uint32_t off) {
    return off ^ ((off >> 3) & 0x70);
}
__device__ __forceinline__ void ldsm_x4(uint32_t* r, uint32_t addr) {
    asm volatile("ldmatrix.sync.aligned.m8n8.x4.shared.b16 {%0,%1,%2,%3}, [%4];"
        : "=r"(r[0]), "=r"(r[1]), "=r"(r[2]), "=r"(r[3]) : "r"(addr));
}
__device__ __forceinline__ void ldsm_x4_t(uint32_t* r, uint32_t addr) {
    asm volatile("ldmatrix.sync.aligned.m8n8.x4.trans.shared.b16 {%0,%1,%2,%3}, [%4];"
        : "=r"(r[0]), "=r"(r[1]), "=r"(r[2]), "=r"(r[3]) : "r"(addr));
}
__device__ __forceinline__ void mma_bf16(float* d, const uint32_t* a,
                                         uint32_t b0, uint32_t b1) {
    asm volatile(
        "mma.sync.aligned.m16n8k16.row.col.f32.bf16.bf16.f32 "
        "{%0,%1,%2,%3}, {%4,%5,%6,%7}, {%8,%9}, {%0,%1,%2,%3};\n"
        : "+f"(d[0]), "+f"(d[1]), "+f"(d[2]), "+f"(d[3])
        : "r"(a[0]), "r"(a[1]), "r"(a[2]), "r"(a[3]), "r"(b0), "r"(b1));
}
__device__ __forceinline__ __nv_bfloat162 pack_bf2(float a, float b) {
    return __floats2bfloat162_rn(a, b);
}
// window-order token -> image-order token
__device__ __forceinline__ int w2i(int t) {
    int widx = t / Ntok, n = t - widx * Ntok;
    int b = widx >> 6, wi = widx & 63;
    int r = (wi >> 3) * WS + n / WS;
    int c = (wi & 7) * WS + n % WS;
    int sh = r + SS; if (sh >= Hh) sh -= Hh;
    int sw = c + SS; if (sw >= Wd) sw -= Wd;
    return b * (Hh * Wd) + sh * Wd + sw;
}

// ---------------- single-launch weight transpose + bf16 ----------------
__global__ void k_transpose_all(const float* __restrict__ qkv_w, const float* __restrict__ proj_w,
                                const float* __restrict__ fc1_w, const float* __restrict__ fc2_w,
                                __nv_bfloat16* __restrict__ wt) {
    int t = blockIdx.x;
    const float* W; __nv_bfloat16* Wt; int K, N, tile, ntx;
    if (t < 432)       { W = qkv_w;  Wt = wt + WT_QKV;  K = Cc;   N = ThreeC; tile = t;        ntx = 36; }
    else if (t < 576)  { W = proj_w; Wt = wt + WT_PROJ; K = Cc;   N = Cc;     tile = t - 432;  ntx = 12; }
    else if (t < 1152) { W = fc1_w;  Wt = wt + WT_FC1;  K = Cc;   N = MLPH;   tile = t - 576;  ntx = 48; }
    else               { W = fc2_w;  Wt = wt + WT_FC2;  K = MLPH; N = Cc;     tile = t - 1152; ntx = 12; }
    int n0 = (tile % ntx) * 32, k0 = (tile / ntx) * 32;

    __shared__ float sm[32][33];
    int tx = threadIdx.x, ty = threadIdx.y;
    #pragma unroll
    for (int i = 0; i < 32; i += 8)
        sm[ty + i][tx] = W[(size_t)(k0 + ty + i) * N + n0 + tx];
    __syncthreads();
    #pragma unroll
    for (int i = 0; i < 32; i += 8)
        Wt[(size_t)(n0 + ty + i) * K + k0 + tx] = __float2bfloat16_rn(sm[tx][ty + i]);
}

// ---------------- build 48 bias+mask logit tables (once per launch) -------------
// blockIdx = cls*NHd + hh ; cls = (wh==7)*2 + (ww==7)
__global__ __launch_bounds__(256)
void k_build_tbl(const float* __restrict__ rpb, __nv_bfloat16* __restrict__ tbl) {
    int cls = blockIdx.x / NHd, hh = blockIdx.x % NHd;
    int wh = (cls >> 1) ? 7 : 0, ww = (cls & 1) ? 7 : 0;
    __shared__ float sb[169];
    __shared__ int   rg[Ntok];
    int tid = threadIdx.x;
    for (int idx = tid; idx < 169; idx += 256) sb[idx] = rpb[idx * NHd + hh];
    if (tid < Ntok) {
        int r = wh * WS + tid / WS, c = ww * WS + tid % WS;
        int hr = (r < Hh - WS) ? 0 : ((r < Hh - SS) ? 1 : 2);
        int wr = (c < Wd - WS) ? 0 : ((c < Wd - SS) ? 1 : 2);
        rg[tid] = hr * 3 + wr;
    }
    __syncthreads();
    __nv_bfloat16* dst = tbl + (size_t)blockIdx.x * 4096;
    for (int idx = tid; idx < 4096; idx += 256) {
        int i = idx >> 6, j = idx & 63;
        float v = -1e4f;
        if (i < Ntok && j < Ntok) {
            int id = i / 7, im = i - id * 7;
            int jd = j / 7, jm = j - jd * 7;
            v = sb[(id - jd + 6) * 13 + (im - jm + 6)];
            if (rg[i] != rg[j]) v -= 100.f;
        }
        dst[idx] = __float2bfloat16_rn(v);
    }
}

// ---------------- bf16 mma.sync GEMM, 128x128 tile, 256 thr, 2 CTAs/SM ----------
constexpr int GBM = 128, GBN = 128;
constexpr int ASTB = GBM * 64;
constexpr int BSTB = GBN * 64;
constexpr int STB  = ASTB + BSTB;
constexpr int SMEM_GEMM = 4 * STB;        // 65536

template <int OT, typename OutT>
__global__ __launch_bounds__(256, 2)
void k_gemm_bf(const __nv_bfloat16* __restrict__ A, const __nv_bfloat16* __restrict__ Wt,
               const float* __restrict__ bias, const float* __restrict__ res,
               OutT* __restrict__ Cm, int M, int N, int K) {
    extern __shared__ char smem[];
    uint32_t sbase = smem_u32(smem);

    const int tid  = threadIdx.x;
    const int lane = tid & 31, warp = tid >> 5;
    const int wm = warp >> 1, wn = warp & 1;
    const int g = lane >> 2, q = lane & 3;
    const int row0 = blockIdx.y * GBM, col0 = blockIdx.x * GBN;
    const int KT = K / 32;

    const __nv_bfloat16* Ab = A  + (size_t)row0 * K;
    const __nv_bfloat16* Bb = Wt + (size_t)col0 * K;

    uint32_t a_off[2], b_off[4];
    {
        int rowa = wm * 32 + (lane & 15);
        int sega = lane >> 4;
        #pragma unroll
        for (int mi = 0; mi < 2; mi++)
            a_off[mi] = swz64((uint32_t)(rowa + mi * 16) * 64 + sega * 16);
        int rowb = wn * 64 + (lane & 7) + ((lane >> 4) << 3);
        int segb = (lane >> 3) & 1;
        #pragma unroll
        for (int p = 0; p < 4; p++)
            b_off[p] = ASTB + swz64((uint32_t)(rowb + p * 16) * 64 + segb * 16);
    }

    float acc[2][8][4];
    #pragma unroll
    for (int i = 0; i < 2; i++)
        #pragma unroll
        for (int j = 0; j < 8; j++)
            #pragma unroll
            for (int r = 0; r < 4; r++) acc[i][j][r] = 0.f;

    auto load_stage = [&](int kt, int s) {
        uint32_t sA = sbase + (uint32_t)s * STB;
        uint32_t sB = sA + ASTB;
        const __nv_bfloat16* Ap = Ab + kt * 32;
        const __nv_bfloat16* Bp = Bb + kt * 32;
        #pragma unroll
        for (int i = 0; i < 2; i++) {
            int c = tid + i * 256, r = c >> 2, cc = c & 3;
            CP16(sA + swz64((uint32_t)(r * 64 + cc * 16)), Ap + (size_t)r * K + cc * 8);
        }
        #pragma unroll
        for (int i = 0; i < 2; i++) {
            int c = tid + i * 256, r = c >> 2, cc = c & 3;
            CP16(sB + swz64((uint32_t)(r * 64 + cc * 16)), Bp + (size_t)r * K + cc * 8);
        }
    };

    load_stage(0, 0); CP_COMMIT();
    load_stage(1, 1); CP_COMMIT();
    load_stage(2, 2); CP_COMMIT();

    for (int kt = 0; kt < KT; kt++) {
        CP_WAIT2();
        __syncthreads();
        uint32_t st = sbase + (uint32_t)(kt & 3) * STB;
        #pragma unroll
        for (int ks = 0; ks < 2; ks++) {
            const uint32_t kx = (uint32_t)ks * 0x20;
            uint32_t a[2][4], b[4][4];
            #pragma unroll
            for (int mi = 0; mi < 2; mi++) ldsm_x4(a[mi], st + (a_off[mi] ^ kx));
            #pragma unroll
            for (int p = 0; p < 4; p++)    ldsm_x4(b[p],  st + (b_off[p]  ^ kx));
            #pragma unroll
            for (int mi = 0; mi < 2; mi++)
                #pragma unroll
                for (int p = 0; p < 4; p++) {
                    mma_bf16(acc[mi][2 * p],     a[mi], b[p][0], b[p][1]);
                    mma_bf16(acc[mi][2 * p + 1], a[mi], b[p][2], b[p][3]);
                }
        }
        if (kt + 3 < KT) load_stage(kt + 3, (kt + 3) & 3);
        CP_COMMIT();
    }

    // ---- epilogue ----
    #pragma unroll
    for (int mi = 0; mi < 2; mi++) {
        int rA = row0 + wm * 32 + mi * 16 + g;
        int rB = rA + 8;
        const float* resA = nullptr; const float* resB = nullptr;
        OutT* outA; OutT* outB;
        if (OT == 4) {
            resA = res + (size_t)w2i(rA) * N;
            resB = res + (size_t)w2i(rB) * N;
            outA = Cm + (size_t)rA * N; outB = Cm + (size_t)rB * N;
        } else if (OT == 5) {
            resA = res + (size_t)rA * N;
            resB = res + (size_t)rB * N;
            outA = Cm + (size_t)w2i(rA) * N; outB = Cm + (size_t)w2i(rB) * N;
        } else {
            outA = Cm + (size_t)rA * N; outB = Cm + (size_t)rB * N;
        }
        #pragma unroll
        for (int ni = 0; ni < 8; ni++) {
            int c = col0 + wn * 64 + ni * 8 + q * 2;
            float b0 = bias[c], b1 = bias[c + 1];
            float v0 = acc[mi][ni][0] + b0;
            float v1 = acc[mi][ni][1] + b1;
            float v2 = acc[mi][ni][2] + b0;
            float v3 = acc[mi][ni][3] + b1;
            if (OT == 1) {
                v0 = 0.5f * v0 * (1.f + erff(v0 * 0.70710678118654752f));
                v1 = 0.5f * v1 * (1.f + erff(v1 * 0.70710678118654752f));
                v2 = 0.5f * v2 * (1.f + erff(v2 * 0.70710678118654752f));
                v3 = 0.5f * v3 * (1.f + erff(v3 * 0.70710678118654752f));
            }
            if (OT >= 4) {
                float2 ra = *(const float2*)&resA[c];
                float2 rb = *(const float2*)&resB[c];
                v0 += ra.x; v1 += ra.y; v2 += rb.x; v3 += rb.y;
            }
            if (OT <= 1) {
                *(__nv_bfloat162*)&((__nv_bfloat16*)outA)[c] = pack_bf2(v0, v1);
                *(__nv_bfloat162*)&((__nv_bfloat16*)outB)[c] = pack_bf2(v2, v3);
            } else {
                *(float2*)&((float*)outA)[c] = make_float2(v0, v1);
                *(float2*)&((float*)outB)[c] = make_float2(v2, v3);
            }
        }
    }
}

// ---------------- LN, warp-per-row (8 rows / 256-thr block) ----------------
template <bool GATHER>
__global__ __launch_bounds__(256)
void k_ln(const float* __restrict__ x, const float* __restrict__ w,
          const float* __restrict__ bi, __nv_bfloat16* __restrict__ out) {
    int warp = threadIdx.x >> 5, lane = threadIdx.x & 31;
    int t = blockIdx.x * 8 + warp;
    const float* src = x + (size_t)(GATHER ? w2i(t) : t) * Cc;

    float2 v[6]; float s = 0.f, s2 = 0.f;
    #pragma unroll
    for (int i = 0; i < 6; i++) {
        v[i] = *(const float2*)&src[(lane + i * 32) * 2];
        s  += v[i].x + v[i].y;
        s2 += v[i].x * v[i].x + v[i].y * v[i].y;
    }
    #pragma unroll
    for (int o = 16; o > 0; o >>= 1) {
        s  += __shfl_xor_sync(0xFFFFFFFFu, s,  o);
        s2 += __shfl_xor_sync(0xFFFFFFFFu, s2, o);
    }
    float mean = s * (1.f / Cc);
    float var  = s2 * (1.f / Cc) - mean * mean;
    float inv  = rsqrtf(var + 1e-5f);
    __nv_bfloat162* dst = (__nv_bfloat162*)(out + (size_t)t * Cc);
    #pragma unroll
    for (int i = 0; i < 6; i++) {
        int c = (lane + i * 32) * 2;
        float2 wv = *(const float2*)&w[c];
        float2 bv = *(const float2*)&bi[c];
        float a = (v[i].x - mean) * inv * wv.x + bv.x;
        float b = (v[i].y - mean) * inv * wv.y + bv.y;
        dst[lane + i * 32] = pack_bf2(a, b);
    }
}

// ---------------- tensor-core attention, precomputed logit table -------
// smem: Q 0 | K 4096 | V 8192 | table/P 12288 (8KB, swz128)
__global__ __launch_bounds__(128)
void k_attn(const __nv_bfloat16* __restrict__ qkv, const __nv_bfloat16* __restrict__ tbl,
            __nv_bfloat16* __restrict__ out) {
    __shared__ __align__(1024) char smem[20480];
    uint32_t sb = smem_u32(smem);

    int blk = blockIdx.x;
    int widx = blk / NHd, hh = blk % NHd;
    int wi = widx % NWim;
    int cls = (((wi >> 3) == 7) ? 2 : 0) + (((wi & 7) == 7) ? 1 : 0);
    int tid = threadIdx.x, lane = tid & 31, warp = tid >> 5;
    int g = lane >> 2, q = lane & 3;

    // ---- load Q,K,V (rows 0-48) + zero pad rows 49-63 + logit table ----
    const __nv_bfloat16* base0 = qkv + (size_t)(widx * Ntok) * ThreeC + hh * HD;
    for (int idx = tid; idx < 196; idx += 128) {
        int row = idx >> 2, seg = idx & 3;
        const __nv_bfloat16* p = base0 + (size_t)row * ThreeC + seg * 8;
        uint32_t d = swz64((uint32_t)(row * 64 + seg * 16));
        *(uint4*)(smem + d)        = *(const uint4*)(p);
        *(uint4*)(smem + 4096 + d) = *(const uint4*)(p + Cc);
        *(uint4*)(smem + 8192 + d) = *(const uint4*)(p + 2 * Cc);
    }
    for (int idx = 196 + tid; idx < 256; idx += 128) {
        int row = idx >> 2, seg = idx & 3;
        uint32_t d = swz64((uint32_t)(row * 64 + seg * 16));
        uint4 z = make_uint4(0, 0, 0, 0);
        *(uint4*)(smem + d)        = z;
        *(uint4*)(smem + 4096 + d) = z;
        *(uint4*)(smem + 8192 + d) = z;
    }
    {   // table slice: 512 uint4 chunks, swz128 into P region
        const uint4* tsrc = (const uint4*)(tbl + (size_t)(cls * NHd + hh) * 4096);
        #pragma unroll
        for (int i = 0; i < 4; i++) {
            int idx = tid + i * 128;
            int row = idx >> 3, seg = idx & 7;
            *(uint4*)(smem + 12288 + swz128((uint32_t)(row * 128 + seg * 16))) = tsrc[idx];
        }
    }
    __syncthreads();

    // ---- S = Q K^T (64x64, K=32) ----
    float acc[8][4];
    #pragma unroll
    for (int i = 0; i < 8; i++)
        #pragma unroll
        for (int r = 0; r < 4; r++) acc[i][r] = 0.f;
    {
        uint32_t aoff = swz64((uint32_t)(warp * 16 + (lane & 15)) * 64 + (lane >> 4) * 16);
        int rowb = (lane & 7) + ((lane >> 4) << 3);
        uint32_t segb = ((lane >> 3) & 1) * 16;
        uint32_t boff[4];
        #pragma unroll
        for (int p = 0; p < 4; p++)
            boff[p] = 4096u + swz64((uint32_t)(rowb + p * 16) * 64 + segb);
        #pragma unroll
        for (int kk = 0; kk < 2; kk++) {
            uint32_t kx = (uint32_t)kk * 32;
            uint32_t a[4];
            ldsm_x4(a, sb + (aoff ^ kx));
            #pragma unroll
            for (int p = 0; p < 4; p++) {
                uint32_t b[4];
                ldsm_x4(b, sb + (boff[p] ^ kx));
                mma_bf16(acc[2 * p],     a, b[0], b[1]);
                mma_bf16(acc[2 * p + 1], a, b[2], b[3]);
            }
        }
    }

    // ---- softmax via swizzled table lookups (conflict-free) ----
    const float scl = 0.17677669529663687f;
    int i1 = warp * 16 + g, i2 = i1 + 8;
    bool v1 = i1 < Ntok, v2 = i2 < Ntok;
    // swz128 on (i*128 + c), c<128: c bits[6:4] ^= (i&7)<<4 ; i1&7 == i2&7 == g
    const char* t1 = smem + 12288 + i1 * 128 + q * 4;
    const char* t2 = smem + 12288 + i2 * 128 + q * 4;
    float mx1 = -1e30f, mx2 = -1e30f;
    #pragma unroll
    for (int ni = 0; ni < 8; ni++) {
        uint32_t co = (uint32_t)((ni ^ g) * 16);
        float2 b1 = __bfloat1622float2(*(const __nv_bfloat162*)(t1 + co));
        float2 b2 = __bfloat1622float2(*(const __nv_bfloat162*)(t2 + co));
        float t;
        t = fmaf(acc[ni][0], scl, b1.x); acc[ni][0] = t; mx1 = fmaxf(mx1, t);
        t = fmaf(acc[ni][1], scl, b1.y); acc[ni][1] = t; mx1 = fmaxf(mx1, t);
        t = fmaf(acc[ni][2], scl, b2.x); acc[ni][2] = t; mx2 = fmaxf(mx2, t);
        t = fmaf(acc[ni][3], scl, b2.y); acc[ni][3] = t; mx2 = fmaxf(mx2, t);
    }
    mx1 = fmaxf(mx1, __shfl_xor_sync(0xFFFFFFFFu, mx1, 1));
    mx1 = fmaxf(mx1, __shfl_xor_sync(0xFFFFFFFFu, mx1, 2));
    mx2 = fmaxf(mx2, __shfl_xor_sync(0xFFFFFFFFu, mx2, 1));
    mx2 = fmaxf(mx2, __shfl_xor_sync(0xFFFFFFFFu, mx2, 2));
    float s1 = 0.f, s2 = 0.f;
    #pragma unroll
    for (int ni = 0; ni < 8; ni++) {
        float e0 = __expf(acc[ni][0] - mx1); acc[ni][0] = e0;
        float e1 = __expf(acc[ni][1] - mx1); acc[ni][1] = e1; s1 += e0 + e1;
        float e2 = __expf(acc[ni][2] - mx2); acc[ni][2] = e2;
        float e3 = __expf(acc[ni][3] - mx2); acc[ni][3] = e3; s2 += e2 + e3;
    }
    s1 += __shfl_xor_sync(0xFFFFFFFFu, s1, 1);
    s1 += __shfl_xor_sync(0xFFFFFFFFu, s1, 2);
    s2 += __shfl_xor_sync(0xFFFFFFFFu, s2, 1);
    s2 += __shfl_xor_sync(0xFFFFFFFFu, s2, 2);
    float n1 = v1 ? (1.f / s1) : 0.f;
    float n2 = v2 ? (1.f / s2) : 0.f;
    __syncwarp();   // this warp's table rows fully read before P overwrite (warp-private)

    // ---- store P (bf16) into swizzled 128B-row buffer (warp-private rows) ----
    #pragma unroll
    for (int ni = 0; ni < 8; ni++) {
        uint32_t cb = (uint32_t)(ni * 8 + q * 2) * 2;
        uint32_t o1 = 12288u + swz128((uint32_t)i1 * 128 + cb);
        uint32_t o2 = 12288u + swz128((uint32_t)i2 * 128 + cb);
        *(__nv_bfloat162*)(smem + o1) = pack_bf2(acc[ni][0] * n1, acc[ni][1] * n1);
        *(__nv_bfloat162*)(smem + o2) = pack_bf2(acc[ni][2] * n2, acc[ni][3] * n2);
    }
    __syncwarp();

    // ---- O = P V  (64x32, K=64) ----
    float acc2[4][4];
    #pragma unroll
    for (int i = 0; i < 4; i++)
        #pragma unroll
        for (int r = 0; r < 4; r++) acc2[i][r] = 0.f;
    {
        uint32_t a2off = 12288u + swz128((uint32_t)(warp * 16 + (lane & 15)) * 128 + (lane >> 4) * 16);
        int rv = (lane & 7) + ((lane >> 3) & 1) * 8;
        uint32_t dv8 = (uint32_t)((lane >> 4) << 3);
        uint32_t voff0 = 8192u + swz64((uint32_t)rv * 64 + dv8 * 2);
        uint32_t voff1 = 8192u + swz64((uint32_t)rv * 64 + (16 + dv8) * 2);
        #pragma unroll
        for (int ks = 0; ks < 4; ks++) {
            uint32_t a2[4], b0[4], b1[4];
            ldsm_x4(a2, sb + (a2off ^ ((uint32_t)ks * 32)));
            ldsm_x4_t(b0, sb + voff0 + (uint32_t)ks * 1024);
            ldsm_x4_t(b1, sb + voff1 + (uint32_t)ks * 1024);
            mma_bf16(acc2[0], a2, b0[0], b0[1]);
            mma_bf16(acc2[1], a2, b0[2], b0[3]);
            mma_bf16(acc2[2], a2, b1[0], b1[1]);
            mma_bf16(acc2[3], a2, b1[2], b1[3]);
        }
    }

    if (v1) {
        __nv_bfloat16* d = out + (size_t)(widx * Ntok + i1) * Cc + hh * HD + q * 2;
        #pragma unroll
        for (int dt = 0; dt < 4; dt++)
            *(__nv_bfloat162*)(d + dt * 8) = pack_bf2(acc2[dt][0], acc2[dt][1]);
    }
    if (v2) {
        __nv_bfloat16* d = out + (size_t)(widx * Ntok + i2) * Cc + hh * HD + q * 2;
        #pragma unroll
        for (int dt = 0; dt < 4; dt++)
            *(__nv_bfloat162*)(d + dt * 8) = pack_bf2(acc2[dt][2], acc2[dt][3]);
    }
}

// ---------------- host launch ----------------
extern "C" void kernel_launch(void* const* d_in, const int* in_sizes, int n_in,
                              void* d_out, int out_size) {
    const float* x      = (const float*)d_in[0];
    const float* n1w    = (const float*)d_in[1];
    const float* n1b    = (const float*)d_in[2];
    const float* qkv_w  = (const float*)d_in[3];
    const float* qkv_b  = (const float*)d_in[4];
    const float* rpb    = (const float*)d_in[5];
    const float* proj_w = (const float*)d_in[6];
    const float* proj_b = (const float*)d_in[7];
    const float* n2w    = (const float*)d_in[8];
    const float* n2b    = (const float*)d_in[9];
    const float* fc1_w  = (const float*)d_in[10];
    const float* fc1_b  = (const float*)d_in[11];
    const float* fc2_w  = (const float*)d_in[12];
    const float* fc2_b  = (const float*)d_in[13];
    float* out = (float*)d_out;

    __nv_bfloat16 *p_xw, *p_qkv, *p_attb, *p_h, *p_f1, *p_wt, *p_tbl;
    float *p_x2w;
    cudaGetSymbolAddress((void**)&p_xw,   g_xw);
    cudaGetSymbolAddress((void**)&p_qkv,  g_qkv);
    cudaGetSymbolAddress((void**)&p_attb, g_attb);
    cudaGetSymbolAddress((void**)&p_x2w,  g_x2w);
    cudaGetSymbolAddress((void**)&p_h,    g_h);
    cudaGetSymbolAddress((void**)&p_f1,   g_f1);
    cudaGetSymbolAddress((void**)&p_wt,   g_wt);
    cudaGetSymbolAddress((void**)&p_tbl,  g_tbl);

    cudaFuncSetAttribute(k_gemm_bf<0, __nv_bfloat16>, cudaFuncAttributeMaxDynamicSharedMemorySize, SMEM_GEMM);
    cudaFuncSetAttribute(k_gemm_bf<1, __nv_bfloat16>, cudaFuncAttributeMaxDynamicSharedMemorySize, SMEM_GEMM);
    cudaFuncSetAttribute(k_gemm_bf<4, float>,         cudaFuncAttributeMaxDynamicSharedMemorySize, SMEM_GEMM);
    cudaFuncSetAttribute(k_gemm_bf<5, float>,         cudaFuncAttributeMaxDynamicSharedMemorySize, SMEM_GEMM);

    // 0. transpose + bf16 weights, and build 48 logit tables
    k_transpose_all<<<1728, dim3(32, 8)>>>(qkv_w, proj_w, fc1_w, fc2_w, p_wt);
    k_build_tbl<<<4 * NHd, 256>>>(rpb, p_tbl);

    // 1. LN1 + shift + window partition (gather)
    k_ln<true><<<Mrows / 8, 256>>>(x, n1w, n1b, p_xw);

    // 2. QKV GEMM -> bf16
    k_gemm_bf<0, __nv_bfloat16><<<dim3(ThreeC/GBN, Mrows/GBM), 256, SMEM_GEMM>>>(
        p_xw, p_wt + WT_QKV, qkv_b, nullptr, p_qkv, Mrows, ThreeC, Cc);

    // 3. tensor-core windowed attention -> bf16
    k_attn<<<(Bn * NWim) * NHd, 128>>>(p_qkv, p_tbl, p_attb);

    // 4. proj GEMM + gathered residual -> x2w (f32, window order)
    k_gemm_bf<4, float><<<dim3(Cc/GBN, Mrows/GBM), 256, SMEM_GEMM>>>(
        p_attb, p_wt + WT_PROJ, proj_b, x, p_x2w, Mrows, Cc, Cc);

    // 5. LN2 (window order)
    k_ln<false><<<Mrows / 8, 256>>>(p_x2w, n2w, n2b, p_h);

    // 6. fc1 GEMM + GELU -> bf16
    k_gemm_bf<1, __nv_bfloat16><<<dim3(MLPH/GBN, Mrows/GBM), 256, SMEM_GEMM>>>(
        p_h, p_wt + WT_FC1, fc1_b, nullptr, p_f1, Mrows, MLPH, Cc);

    // 7. fc2 GEMM + bias + residual, scattered to image order -> d_out
    k_gemm_bf<5, float><<<dim3(Cc/GBN, Mrows/GBM), 256, SMEM_GEMM>>>(
        p_f1, p_wt + WT_FC2, fc2_b, p_x2w, out, Mrows, Cc, MLPH);
}

// round 17
// speedup vs baseline: 1.1192x; 1.0494x over previous
#include <cuda_runtime.h>
#include <cuda_bf16.h>
#include <math.h>
#include <stdint.h>

// ---------------- problem constants ----------------
constexpr int Bn   = 32;
constexpr int Hh   = 56;
constexpr int Wd   = 56;
constexpr int Cc   = 384;
constexpr int NHd  = 12;
constexpr int WS   = 7;
constexpr int SS   = 3;
constexpr int Ntok = WS * WS;            // 49
constexpr int NWim = (Hh/WS) * (Wd/WS);  // 64
constexpr int HD   = Cc / NHd;           // 32
constexpr int MLPH = 4 * Cc;             // 1536
constexpr int Mrows = Bn * Hh * Wd;      // 100352
constexpr int ThreeC = 3 * Cc;           // 1152

// ---------------- scratch (device globals) ----------------
__device__ __nv_bfloat16 g_xw  [(size_t)Mrows * Cc];
__device__ __nv_bfloat16 g_qkv [(size_t)Mrows * ThreeC];
__device__ __nv_bfloat16 g_attb[(size_t)Mrows * Cc];
__device__ float         g_x2w [(size_t)Mrows * Cc];
__device__ __nv_bfloat16 g_h   [(size_t)Mrows * Cc];
__device__ __nv_bfloat16 g_f1  [(size_t)Mrows * MLPH];
__device__ __nv_bfloat16 g_tbl [4 * NHd * 64 * 64];
constexpr size_t WT_QKV  = 0;
constexpr size_t WT_PROJ = WT_QKV  + (size_t)Cc * ThreeC;
constexpr size_t WT_FC1  = WT_PROJ + (size_t)Cc * Cc;
constexpr size_t WT_FC2  = WT_FC1  + (size_t)Cc * MLPH;
__device__ __nv_bfloat16 g_wt[WT_FC2 + (size_t)MLPH * Cc];

// ---------------- helpers ----------------
__device__ __forceinline__ uint32_t smem_u32(const void* p) {
    uint32_t a;
    asm("{ .reg .u64 t; cvta.to.shared.u64 t, %1; cvt.u32.u64 %0, t; }" : "=r"(a) : "l"(p));
    return a;
}
#define CP16(dst, src) asm volatile("cp.async.cg.shared.global [%0], [%1], 16;\n" :: "r"(dst), "l"(src))
#define CP_COMMIT()    asm volatile("cp.async.commit_group;\n" ::: "memory")
#define CP_WAIT1()     asm volatile("cp.async.wait_group 1;\n" ::: "memory")

__device__ __forceinline__ uint32_t swz64(uint32_t off) {
    return off ^ ((off >> 3) & 0x30);
}
__device__ __forceinline__ uint32_t swz128(uint32_t off) {
    return off ^ ((off >> 3) & 0x70);
}
__device__ __forceinline__ void ldsm_x4(uint32_t* r, uint32_t addr) {
    asm volatile("ldmatrix.sync.aligned.m8n8.x4.shared.b16 {%0,%1,%2,%3}, [%4];"
        : "=r"(r[0]), "=r"(r[1]), "=r"(r[2]), "=r"(r[3]) : "r"(addr));
}
__device__ __forceinline__ void ldsm_x4_t(uint32_t* r, uint32_t addr) {
    asm volatile("ldmatrix.sync.aligned.m8n8.x4.trans.shared.b16 {%0,%1,%2,%3}, [%4];"
        : "=r"(r[0]), "=r"(r[1]), "=r"(r[2]), "=r"(r[3]) : "r"(addr));
}
__device__ __forceinline__ void mma_bf16(float* d, const uint32_t* a,
                                         uint32_t b0, uint32_t b1) {
    asm volatile(
        "mma.sync.aligned.m16n8k16.row.col.f32.bf16.bf16.f32 "
        "{%0,%1,%2,%3}, {%4,%5,%6,%7}, {%8,%9}, {%0,%1,%2,%3};\n"
        : "+f"(d[0]), "+f"(d[1]), "+f"(d[2]), "+f"(d[3])
        : "r"(a[0]), "r"(a[1]), "r"(a[2]), "r"(a[3]), "r"(b0), "r"(b1));
}
__device__ __forceinline__ __nv_bfloat162 pack_bf2(float a, float b) {
    return __floats2bfloat162_rn(a, b);
}
// window-order token -> image-order token
__device__ __forceinline__ int w2i(int t) {
    int widx = t / Ntok, n = t - widx * Ntok;
    int b = widx >> 6, wi = widx & 63;
    int r = (wi >> 3) * WS + n / WS;
    int c = (wi & 7) * WS + n % WS;
    int sh = r + SS; if (sh >= Hh) sh -= Hh;
    int sw = c + SS; if (sw >= Wd) sw -= Wd;
    return b * (Hh * Wd) + sh * Wd + sw;
}

// ---------------- single-launch weight transpose + bf16 ----------------
__global__ void k_transpose_all(const float* __restrict__ qkv_w, const float* __restrict__ proj_w,
                                const float* __restrict__ fc1_w, const float* __restrict__ fc2_w,
                                __nv_bfloat16* __restrict__ wt) {
    int t = blockIdx.x;
    const float* W; __nv_bfloat16* Wt; int K, N, tile, ntx;
    if (t < 432)       { W = qkv_w;  Wt = wt + WT_QKV;  K = Cc;   N = ThreeC; tile = t;        ntx = 36; }
    else if (t < 576)  { W = proj_w; Wt = wt + WT_PROJ; K = Cc;   N = Cc;     tile = t - 432;  ntx = 12; }
    else if (t < 1152) { W = fc1_w;  Wt = wt + WT_FC1;  K = Cc;   N = MLPH;   tile = t - 576;  ntx = 48; }
    else               { W = fc2_w;  Wt = wt + WT_FC2;  K = MLPH; N = Cc;     tile = t - 1152; ntx = 12; }
    int n0 = (tile % ntx) * 32, k0 = (tile / ntx) * 32;

    __shared__ float sm[32][33];
    int tx = threadIdx.x, ty = threadIdx.y;
    #pragma unroll
    for (int i = 0; i < 32; i += 8)
        sm[ty + i][tx] = W[(size_t)(k0 + ty + i) * N + n0 + tx];
    __syncthreads();
    #pragma unroll
    for (int i = 0; i < 32; i += 8)
        Wt[(size_t)(n0 + ty + i) * K + k0 + tx] = __float2bfloat16_rn(sm[tx][ty + i]);
}

// ---------------- build 48 bias+mask logit tables ----------------
__global__ __launch_bounds__(256)
void k_build_tbl(const float* __restrict__ rpb, __nv_bfloat16* __restrict__ tbl) {
    int cls = blockIdx.x / NHd, hh = blockIdx.x % NHd;
    int wh = (cls >> 1) ? 7 : 0, ww = (cls & 1) ? 7 : 0;
    __shared__ float sb[169];
    __shared__ int   rg[Ntok];
    int tid = threadIdx.x;
    for (int idx = tid; idx < 169; idx += 256) sb[idx] = rpb[idx * NHd + hh];
    if (tid < Ntok) {
        int r = wh * WS + tid / WS, c = ww * WS + tid % WS;
        int hr = (r < Hh - WS) ? 0 : ((r < Hh - SS) ? 1 : 2);
        int wr = (c < Wd - WS) ? 0 : ((c < Wd - SS) ? 1 : 2);
        rg[tid] = hr * 3 + wr;
    }
    __syncthreads();
    __nv_bfloat16* dst = tbl + (size_t)blockIdx.x * 4096;
    for (int idx = tid; idx < 4096; idx += 256) {
        int i = idx >> 6, j = idx & 63;
        float v = -1e4f;
        if (i < Ntok && j < Ntok) {
            int id = i / 7, im = i - id * 7;
            int jd = j / 7, jm = j - jd * 7;
            v = sb[(id - jd + 6) * 13 + (im - jm + 6)];
            if (rg[i] != rg[j]) v -= 100.f;
        }
        dst[idx] = __float2bfloat16_rn(v);
    }
}

// ---------------- bf16 mma.sync GEMM, 128x128 tile, BK=64, 2 CTAs/SM ----------
// 8 warps (4M x 2N), warp tile 32x64. smem rows 128B swz128, 3 stages x 32KB.
constexpr int GBM = 128, GBN = 128;
constexpr int ASTB = GBM * 128;           // 16384
constexpr int BSTB = GBN * 128;           // 16384
constexpr int STB  = ASTB + BSTB;         // 32768
constexpr int SMEM_GEMM = 3 * STB;        // 98304

template <int OT, typename OutT>
__global__ __launch_bounds__(256, 2)
void k_gemm_bf(const __nv_bfloat16* __restrict__ A, const __nv_bfloat16* __restrict__ Wt,
               const float* __restrict__ bias, const float* __restrict__ res,
               OutT* __restrict__ Cm, int M, int N, int K) {
    extern __shared__ char smem[];
    uint32_t sbase = smem_u32(smem);

    const int tid  = threadIdx.x;
    const int lane = tid & 31, warp = tid >> 5;
    const int wm = warp >> 1, wn = warp & 1;
    const int g = lane >> 2, q = lane & 3;
    const int row0 = blockIdx.y * GBM, col0 = blockIdx.x * GBN;
    const int KT = K / 64;

    const __nv_bfloat16* Ab = A  + (size_t)row0 * K;
    const __nv_bfloat16* Bb = Wt + (size_t)col0 * K;

    // per-thread ldmatrix offsets (stage-relative, ks=0); ks applies as XOR ks*32
    uint32_t a_off[2], b_off[4];
    {
        int rowa = wm * 32 + (lane & 15);
        int sega = lane >> 4;
        #pragma unroll
        for (int mi = 0; mi < 2; mi++)
            a_off[mi] = swz128((uint32_t)(rowa + mi * 16) * 128 + sega * 16);
        int rowb = wn * 64 + (lane & 7) + ((lane >> 4) << 3);
        int segb = ((lane >> 3) & 1) * 16;
        #pragma unroll
        for (int p = 0; p < 4; p++)
            b_off[p] = ASTB + swz128((uint32_t)(rowb + p * 16) * 128 + segb);
    }

    float acc[2][8][4];
    #pragma unroll
    for (int i = 0; i < 2; i++)
        #pragma unroll
        for (int j = 0; j < 8; j++)
            #pragma unroll
            for (int r = 0; r < 4; r++) acc[i][j][r] = 0.f;

    auto load_stage = [&](int kt, int s) {
        uint32_t sA = sbase + (uint32_t)s * STB;
        uint32_t sB = sA + ASTB;
        const __nv_bfloat16* Ap = Ab + kt * 64;
        const __nv_bfloat16* Bp = Bb + kt * 64;
        #pragma unroll
        for (int i = 0; i < 4; i++) {          // A: 1024 chunks of 16B
            int c = tid + i * 256, r = c >> 3, cc = c & 7;
            CP16(sA + swz128((uint32_t)(r * 128 + cc * 16)), Ap + (size_t)r * K + cc * 8);
        }
        #pragma unroll
        for (int i = 0; i < 4; i++) {          // B: 1024 chunks of 16B
            int c = tid + i * 256, r = c >> 3, cc = c & 7;
            CP16(sB + swz128((uint32_t)(r * 128 + cc * 16)), Bp + (size_t)r * K + cc * 8);
        }
    };

    load_stage(0, 0); CP_COMMIT();
    load_stage(1, 1); CP_COMMIT();

    int st_idx = 0;
    for (int kt = 0; kt < KT; kt++) {
        CP_WAIT1();
        __syncthreads();
        uint32_t st = sbase + (uint32_t)st_idx * STB;
        #pragma unroll
        for (int ks = 0; ks < 4; ks++) {
            const uint32_t kx = (uint32_t)ks * 0x20;
            uint32_t a[2][4], b[4][4];
            #pragma unroll
            for (int mi = 0; mi < 2; mi++) ldsm_x4(a[mi], st + (a_off[mi] ^ kx));
            #pragma unroll
            for (int p = 0; p < 4; p++)    ldsm_x4(b[p],  st + (b_off[p]  ^ kx));
            #pragma unroll
            for (int mi = 0; mi < 2; mi++)
                #pragma unroll
                for (int p = 0; p < 4; p++) {
                    mma_bf16(acc[mi][2 * p],     a[mi], b[p][0], b[p][1]);
                    mma_bf16(acc[mi][2 * p + 1], a[mi], b[p][2], b[p][3]);
                }
        }
        if (kt + 2 < KT) {
            int s2 = st_idx + 2; if (s2 >= 3) s2 -= 3;
            load_stage(kt + 2, s2);
        }
        CP_COMMIT();
        if (++st_idx == 3) st_idx = 0;
    }

    // ---- epilogue ----
    #pragma unroll
    for (int mi = 0; mi < 2; mi++) {
        int rA = row0 + wm * 32 + mi * 16 + g;
        int rB = rA + 8;
        const float* resA = nullptr; const float* resB = nullptr;
        OutT* outA; OutT* outB;
        if (OT == 4) {
            resA = res + (size_t)w2i(rA) * N;
            resB = res + (size_t)w2i(rB) * N;
            outA = Cm + (size_t)rA * N; outB = Cm + (size_t)rB * N;
        } else if (OT == 5) {
            resA = res + (size_t)rA * N;
            resB = res + (size_t)rB * N;
            outA = Cm + (size_t)w2i(rA) * N; outB = Cm + (size_t)w2i(rB) * N;
        } else {
            outA = Cm + (size_t)rA * N; outB = Cm + (size_t)rB * N;
        }
        #pragma unroll
        for (int ni = 0; ni < 8; ni++) {
            int c = col0 + wn * 64 + ni * 8 + q * 2;
            float b0 = bias[c], b1 = bias[c + 1];
            float v0 = acc[mi][ni][0] + b0;
            float v1 = acc[mi][ni][1] + b1;
            float v2 = acc[mi][ni][2] + b0;
            float v3 = acc[mi][ni][3] + b1;
            if (OT == 1) {
                v0 = 0.5f * v0 * (1.f + erff(v0 * 0.70710678118654752f));
                v1 = 0.5f * v1 * (1.f + erff(v1 * 0.70710678118654752f));
                v2 = 0.5f * v2 * (1.f + erff(v2 * 0.70710678118654752f));
                v3 = 0.5f * v3 * (1.f + erff(v3 * 0.70710678118654752f));
            }
            if (OT >= 4) {
                float2 ra = *(const float2*)&resA[c];
                float2 rb = *(const float2*)&resB[c];
                v0 += ra.x; v1 += ra.y; v2 += rb.x; v3 += rb.y;
            }
            if (OT <= 1) {
                *(__nv_bfloat162*)&((__nv_bfloat16*)outA)[c] = pack_bf2(v0, v1);
                *(__nv_bfloat162*)&((__nv_bfloat16*)outB)[c] = pack_bf2(v2, v3);
            } else {
                *(float2*)&((float*)outA)[c] = make_float2(v0, v1);
                *(float2*)&((float*)outB)[c] = make_float2(v2, v3);
            }
        }
    }
}

// ---------------- LN, warp-per-row (8 rows / 256-thr block) ----------------
template <bool GATHER>
__global__ __launch_bounds__(256)
void k_ln(const float* __restrict__ x, const float* __restrict__ w,
          const float* __restrict__ bi, __nv_bfloat16* __restrict__ out) {
    int warp = threadIdx.x >> 5, lane = threadIdx.x & 31;
    int t = blockIdx.x * 8 + warp;
    const float* src = x + (size_t)(GATHER ? w2i(t) : t) * Cc;

    float2 v[6]; float s = 0.f, s2 = 0.f;
    #pragma unroll
    for (int i = 0; i < 6; i++) {
        v[i] = *(const float2*)&src[(lane + i * 32) * 2];
        s  += v[i].x + v[i].y;
        s2 += v[i].x * v[i].x + v[i].y * v[i].y;
    }
    #pragma unroll
    for (int o = 16; o > 0; o >>= 1) {
        s  += __shfl_xor_sync(0xFFFFFFFFu, s,  o);
        s2 += __shfl_xor_sync(0xFFFFFFFFu, s2, o);
    }
    float mean = s * (1.f / Cc);
    float var  = s2 * (1.f / Cc) - mean * mean;
    float inv  = rsqrtf(var + 1e-5f);
    __nv_bfloat162* dst = (__nv_bfloat162*)(out + (size_t)t * Cc);
    #pragma unroll
    for (int i = 0; i < 6; i++) {
        int c = (lane + i * 32) * 2;
        float2 wv = *(const float2*)&w[c];
        float2 bv = *(const float2*)&bi[c];
        float a = (v[i].x - mean) * inv * wv.x + bv.x;
        float b = (v[i].y - mean) * inv * wv.y + bv.y;
        dst[lane + i * 32] = pack_bf2(a, b);
    }
}

// ---------------- tensor-core attention, precomputed logit table -------
__global__ __launch_bounds__(128)
void k_attn(const __nv_bfloat16* __restrict__ qkv, const __nv_bfloat16* __restrict__ tbl,
            __nv_bfloat16* __restrict__ out) {
    __shared__ __align__(1024) char smem[20480];
    uint32_t sb = smem_u32(smem);

    int blk = blockIdx.x;
    int widx = blk / NHd, hh = blk % NHd;
    int wi = widx % NWim;
    int cls = (((wi >> 3) == 7) ? 2 : 0) + (((wi & 7) == 7) ? 1 : 0);
    int tid = threadIdx.x, lane = tid & 31, warp = tid >> 5;
    int g = lane >> 2, q = lane & 3;

    const __nv_bfloat16* base0 = qkv + (size_t)(widx * Ntok) * ThreeC + hh * HD;
    for (int idx = tid; idx < 196; idx += 128) {
        int row = idx >> 2, seg = idx & 3;
        const __nv_bfloat16* p = base0 + (size_t)row * ThreeC + seg * 8;
        uint32_t d = swz64((uint32_t)(row * 64 + seg * 16));
        *(uint4*)(smem + d)        = *(const uint4*)(p);
        *(uint4*)(smem + 4096 + d) = *(const uint4*)(p + Cc);
        *(uint4*)(smem + 8192 + d) = *(const uint4*)(p + 2 * Cc);
    }
    for (int idx = 196 + tid; idx < 256; idx += 128) {
        int row = idx >> 2, seg = idx & 3;
        uint32_t d = swz64((uint32_t)(row * 64 + seg * 16));
        uint4 z = make_uint4(0, 0, 0, 0);
        *(uint4*)(smem + d)        = z;
        *(uint4*)(smem + 4096 + d) = z;
        *(uint4*)(smem + 8192 + d) = z;
    }
    {
        const uint4* tsrc = (const uint4*)(tbl + (size_t)(cls * NHd + hh) * 4096);
        #pragma unroll
        for (int i = 0; i < 4; i++) {
            int idx = tid + i * 128;
            int row = idx >> 3, seg = idx & 7;
            *(uint4*)(smem + 12288 + swz128((uint32_t)(row * 128 + seg * 16))) = tsrc[idx];
        }
    }
    __syncthreads();

    float acc[8][4];
    #pragma unroll
    for (int i = 0; i < 8; i++)
        #pragma unroll
        for (int r = 0; r < 4; r++) acc[i][r] = 0.f;
    {
        uint32_t aoff = swz64((uint32_t)(warp * 16 + (lane & 15)) * 64 + (lane >> 4) * 16);
        int rowb = (lane & 7) + ((lane >> 4) << 3);
        uint32_t segb = ((lane >> 3) & 1) * 16;
        uint32_t boff[4];
        #pragma unroll
        for (int p = 0; p < 4; p++)
            boff[p] = 4096u + swz64((uint32_t)(rowb + p * 16) * 64 + segb);
        #pragma unroll
        for (int kk = 0; kk < 2; kk++) {
            uint32_t kx = (uint32_t)kk * 32;
            uint32_t a[4];
            ldsm_x4(a, sb + (aoff ^ kx));
            #pragma unroll
            for (int p = 0; p < 4; p++) {
                uint32_t b[4];
                ldsm_x4(b, sb + (boff[p] ^ kx));
                mma_bf16(acc[2 * p],     a, b[0], b[1]);
                mma_bf16(acc[2 * p + 1], a, b[2], b[3]);
            }
        }
    }

    const float scl = 0.17677669529663687f;
    int i1 = warp * 16 + g, i2 = i1 + 8;
    bool v1 = i1 < Ntok, v2 = i2 < Ntok;
    const char* t1 = smem + 12288 + i1 * 128 + q * 4;
    const char* t2 = smem + 12288 + i2 * 128 + q * 4;
    float mx1 = -1e30f, mx2 = -1e30f;
    #pragma unroll
    for (int ni = 0; ni < 8; ni++) {
        uint32_t co = (uint32_t)((ni ^ g) * 16);
        float2 b1 = __bfloat1622float2(*(const __nv_bfloat162*)(t1 + co));
        float2 b2 = __bfloat1622float2(*(const __nv_bfloat162*)(t2 + co));
        float t;
        t = fmaf(acc[ni][0], scl, b1.x); acc[ni][0] = t; mx1 = fmaxf(mx1, t);
        t = fmaf(acc[ni][1], scl, b1.y); acc[ni][1] = t; mx1 = fmaxf(mx1, t);
        t = fmaf(acc[ni][2], scl, b2.x); acc[ni][2] = t; mx2 = fmaxf(mx2, t);
        t = fmaf(acc[ni][3], scl, b2.y); acc[ni][3] = t; mx2 = fmaxf(mx2, t);
    }
    mx1 = fmaxf(mx1, __shfl_xor_sync(0xFFFFFFFFu, mx1, 1));
    mx1 = fmaxf(mx1, __shfl_xor_sync(0xFFFFFFFFu, mx1, 2));
    mx2 = fmaxf(mx2, __shfl_xor_sync(0xFFFFFFFFu, mx2, 1));
    mx2 = fmaxf(mx2, __shfl_xor_sync(0xFFFFFFFFu, mx2, 2));
    float s1 = 0.f, s2 = 0.f;
    #pragma unroll
    for (int ni = 0; ni < 8; ni++) {
        float e0 = __expf(acc[ni][0] - mx1); acc[ni][0] = e0;
        float e1 = __expf(acc[ni][1] - mx1); acc[ni][1] = e1; s1 += e0 + e1;
        float e2 = __expf(acc[ni][2] - mx2); acc[ni][2] = e2;
        float e3 = __expf(acc[ni][3] - mx2); acc[ni][3] = e3; s2 += e2 + e3;
    }
    s1 += __shfl_xor_sync(0xFFFFFFFFu, s1, 1);
    s1 += __shfl_xor_sync(0xFFFFFFFFu, s1, 2);
    s2 += __shfl_xor_sync(0xFFFFFFFFu, s2, 1);
    s2 += __shfl_xor_sync(0xFFFFFFFFu, s2, 2);
    float n1 = v1 ? (1.f / s1) : 0.f;
    float n2 = v2 ? (1.f / s2) : 0.f;
    __syncwarp();

    #pragma unroll
    for (int ni = 0; ni < 8; ni++) {
        uint32_t cb = (uint32_t)(ni * 8 + q * 2) * 2;
        uint32_t o1 = 12288u + swz128((uint32_t)i1 * 128 + cb);
        uint32_t o2 = 12288u + swz128((uint32_t)i2 * 128 + cb);
        *(__nv_bfloat162*)(smem + o1) = pack_bf2(acc[ni][0] * n1, acc[ni][1] * n1);
        *(__nv_bfloat162*)(smem + o2) = pack_bf2(acc[ni][2] * n2, acc[ni][3] * n2);
    }
    __syncwarp();

    float acc2[4][4];
    #pragma unroll
    for (int i = 0; i < 4; i++)
        #pragma unroll
        for (int r = 0; r < 4; r++) acc2[i][r] = 0.f;
    {
        uint32_t a2off = 12288u + swz128((uint32_t)(warp * 16 + (lane & 15)) * 128 + (lane >> 4) * 16);
        int rv = (lane & 7) + ((lane >> 3) & 1) * 8;
        uint32_t dv8 = (uint32_t)((lane >> 4) << 3);
        uint32_t voff0 = 8192u + swz64((uint32_t)rv * 64 + dv8 * 2);
        uint32_t voff1 = 8192u + swz64((uint32_t)rv * 64 + (16 + dv8) * 2);
        #pragma unroll
        for (int ks = 0; ks < 4; ks++) {
            uint32_t a2[4], b0[4], b1[4];
            ldsm_x4(a2, sb + (a2off ^ ((uint32_t)ks * 32)));
            ldsm_x4_t(b0, sb + voff0 + (uint32_t)ks * 1024);
            ldsm_x4_t(b1, sb + voff1 + (uint32_t)ks * 1024);
            mma_bf16(acc2[0], a2, b0[0], b0[1]);
            mma_bf16(acc2[1], a2, b0[2], b0[3]);
            mma_bf16(acc2[2], a2, b1[0], b1[1]);
            mma_bf16(acc2[3], a2, b1[2], b1[3]);
        }
    }

    if (v1) {
        __nv_bfloat16* d = out + (size_t)(widx * Ntok + i1) * Cc + hh * HD + q * 2;
        #pragma unroll
        for (int dt = 0; dt < 4; dt++)
            *(__nv_bfloat162*)(d + dt * 8) = pack_bf2(acc2[dt][0], acc2[dt][1]);
    }
    if (v2) {
        __nv_bfloat16* d = out + (size_t)(widx * Ntok + i2) * Cc + hh * HD + q * 2;
        #pragma unroll
        for (int dt = 0; dt < 4; dt++)
            *(__nv_bfloat162*)(d + dt * 8) = pack_bf2(acc2[dt][2], acc2[dt][3]);
    }
}

// ---------------- host launch ----------------
extern "C" void kernel_launch(void* const* d_in, const int* in_sizes, int n_in,
                              void* d_out, int out_size) {
    const float* x      = (const float*)d_in[0];
    const float* n1w    = (const float*)d_in[1];
    const float* n1b    = (const float*)d_in[2];
    const float* qkv_w  = (const float*)d_in[3];
    const float* qkv_b  = (const float*)d_in[4];
    const float* rpb    = (const float*)d_in[5];
    const float* proj_w = (const float*)d_in[6];
    const float* proj_b = (const float*)d_in[7];
    const float* n2w    = (const float*)d_in[8];
    const float* n2b    = (const float*)d_in[9];
    const float* fc1_w  = (const float*)d_in[10];
    const float* fc1_b  = (const float*)d_in[11];
    const float* fc2_w  = (const float*)d_in[12];
    const float* fc2_b  = (const float*)d_in[13];
    float* out = (float*)d_out;

    __nv_bfloat16 *p_xw, *p_qkv, *p_attb, *p_h, *p_f1, *p_wt, *p_tbl;
    float *p_x2w;
    cudaGetSymbolAddress((void**)&p_xw,   g_xw);
    cudaGetSymbolAddress((void**)&p_qkv,  g_qkv);
    cudaGetSymbolAddress((void**)&p_attb, g_attb);
    cudaGetSymbolAddress((void**)&p_x2w,  g_x2w);
    cudaGetSymbolAddress((void**)&p_h,    g_h);
    cudaGetSymbolAddress((void**)&p_f1,   g_f1);
    cudaGetSymbolAddress((void**)&p_wt,   g_wt);
    cudaGetSymbolAddress((void**)&p_tbl,  g_tbl);

    cudaFuncSetAttribute(k_gemm_bf<0, __nv_bfloat16>, cudaFuncAttributeMaxDynamicSharedMemorySize, SMEM_GEMM);
    cudaFuncSetAttribute(k_gemm_bf<1, __nv_bfloat16>, cudaFuncAttributeMaxDynamicSharedMemorySize, SMEM_GEMM);
    cudaFuncSetAttribute(k_gemm_bf<4, float>,         cudaFuncAttributeMaxDynamicSharedMemorySize, SMEM_GEMM);
    cudaFuncSetAttribute(k_gemm_bf<5, float>,         cudaFuncAttributeMaxDynamicSharedMemorySize, SMEM_GEMM);

    // 0. transpose + bf16 weights, and build 48 logit tables
    k_transpose_all<<<1728, dim3(32, 8)>>>(qkv_w, proj_w, fc1_w, fc2_w, p_wt);
    k_build_tbl<<<4 * NHd, 256>>>(rpb, p_tbl);

    // 1. LN1 + shift + window partition (gather)
    k_ln<true><<<Mrows / 8, 256>>>(x, n1w, n1b, p_xw);

    // 2. QKV GEMM -> bf16
    k_gemm_bf<0, __nv_bfloat16><<<dim3(ThreeC/GBN, Mrows/GBM), 256, SMEM_GEMM>>>(
        p_xw, p_wt + WT_QKV, qkv_b, nullptr, p_qkv, Mrows, ThreeC, Cc);

    // 3. tensor-core windowed attention -> bf16
    k_attn<<<(Bn * NWim) * NHd, 128>>>(p_qkv, p_tbl, p_attb);

    // 4. proj GEMM + gathered residual -> x2w (f32, window order)
    k_gemm_bf<4, float><<<dim3(Cc/GBN, Mrows/GBM), 256, SMEM_GEMM>>>(
        p_attb, p_wt + WT_PROJ, proj_b, x, p_x2w, Mrows, Cc, Cc);

    // 5. LN2 (window order)
    k_ln<false><<<Mrows / 8, 256>>>(p_x2w, n2w, n2b, p_h);

    // 6. fc1 GEMM + GELU -> bf16
    k_gemm_bf<1, __nv_bfloat16><<<dim3(MLPH/GBN, Mrows/GBM), 256, SMEM_GEMM>>>(
        p_h, p_wt + WT_FC1, fc1_b, nullptr, p_f1, Mrows, MLPH, Cc);

    // 7. fc2 GEMM + bias + residual, scattered to image order -> d_out
    k_gemm_bf<5, float><<<dim3(Cc/GBN, Mrows/GBM), 256, SMEM_GEMM>>>(
        p_f1, p_wt + WT_FC2, fc2_b, p_x2w, out, Mrows, Cc, MLPH);
}